// round 2
// baseline (speedup 1.0000x reference)
#include <cuda_runtime.h>
#include <math.h>

// Problem constants
#define HID    256
#define NINS   2048
#define TTOK   16
#define EMB    512
#define PPAR   8
#define LEVELS 16
#define KLEV   128        // NINS / LEVELS
#define G4     1024       // 4*HID gate width

// ---------------------------------------------------------------------------
// Scratch (device globals; no runtime allocation allowed)
// ---------------------------------------------------------------------------
__device__ float g_Xg [NINS * TTOK * G4];   // token input-gates, row = n*TTOK + t (128 MB)
__device__ float g_X2g[NINS * G4];          // instruction input-gates
__device__ float g_G  [NINS * G4];          // per-step gate buffer
__device__ float g_H  [NINS * HID];         // token-LSTM h  (becomes ins_embed)
__device__ float g_C  [NINS * HID];         // token-LSTM c
__device__ float g_HD [NINS * HID];         // DAG-LSTM H
__device__ float g_CD [NINS * HID];         // DAG-LSTM C
__device__ float g_h0 [KLEV * HID];         // gathered parent h
__device__ float g_c0 [KLEV * HID];         // gathered parent c
__device__ int   g_children[NINS];
__device__ float g_partial[16 * HID];
__device__ int   g_pval_i32;                // 1 if parent_valid arrived as int32

// ---------------------------------------------------------------------------
// parent_valid dtype probe.
// Reading the first NINS*PPAR BYTES is in-bounds under either dtype (the int32
// buffer is 4x larger). If the underlying data is int32 with values {0,1}
// (little-endian), all bytes at offsets !=0 (mod 4) are zero. If it is real
// uint8/bool data, ~75% of entries for levels >= 1 are nonzero, so some byte
// at offset % 4 != 0 is nonzero with certainty (12288 Bernoulli(0.75) draws).
// ---------------------------------------------------------------------------
__global__ void detect_pval_k(const unsigned char* __restrict__ pv) {
    __shared__ int cnt;
    if (threadIdx.x == 0) cnt = 0;
    __syncthreads();
    int local = 0;
    for (int i = KLEV * PPAR + threadIdx.x; i < NINS * PPAR; i += blockDim.x)
        if ((i & 3) && pv[i]) local++;
    if (local) atomicAdd(&cnt, local);
    __syncthreads();
    if (threadIdx.x == 0) g_pval_i32 = (cnt == 0) ? 1 : 0;
}

__device__ __forceinline__ bool pvget(const unsigned char* pv, long i) {
    return g_pval_i32 ? (((const int*)pv)[i] != 0) : (pv[i] != 0);
}

// ---------------------------------------------------------------------------
// Generic SGEMM:  C[M,N] = A[M,K] @ B[N,K]^T  (+ Res[M,N]) (+ bias0[N] + bias1[N])
// B is a weight matrix stored row-major [N,K] (PyTorch layout), so this is x@W^T.
// 256 threads/block, BMxBN tile, TMxTN micro-tile, K-step 8, float4 global loads.
// M,N multiples of BM,BN; K multiple of 8 (true for all call sites).
// ---------------------------------------------------------------------------
template <int BM, int BN, int TM, int TN>
__global__ void __launch_bounds__(256) sgemm_k(
    const float* __restrict__ A, int lda,
    const float* __restrict__ B, int ldb,
    const float* __restrict__ Res, int ldres,
    const float* __restrict__ bias0, const float* __restrict__ bias1,
    float* __restrict__ C, int ldc, int K)
{
    constexpr int KT = 8;
    constexpr int TX = BN / TN;
    constexpr int TY = BM / TM;
    static_assert(TX * TY == 256, "256 threads");
    static_assert(TM % 4 == 0 && TN % 4 == 0, "vector frags");

    __shared__ float As[KT][BM + 4];
    __shared__ float Bs[KT][BN + 4];

    const int tid = threadIdx.x;
    const int tx  = tid % TX;
    const int ty  = tid / TX;
    const long m0 = (long)blockIdx.y * BM;
    const long n0 = (long)blockIdx.x * BN;

    float acc[TM][TN];
#pragma unroll
    for (int i = 0; i < TM; i++)
#pragma unroll
        for (int j = 0; j < TN; j++) acc[i][j] = 0.f;

    constexpr int LA = BM * KT / 256;   // floats per thread for A tile (4 or 2)
    constexpr int TPRA = KT / LA;
    constexpr int LB = BN * KT / 256;
    constexpr int TPRB = KT / LB;
    const int arow = tid / TPRA, akk = (tid % TPRA) * LA;
    const int brow = tid / TPRB, bkk = (tid % TPRB) * LB;

    const float* Ag = A + (m0 + arow) * (long)lda;
    const float* Bg = B + (n0 + brow) * (long)ldb;

    for (int k0 = 0; k0 < K; k0 += KT) {
        if constexpr (LA == 4) {
            float4 v = *reinterpret_cast<const float4*>(Ag + k0 + akk);
            As[akk + 0][arow] = v.x; As[akk + 1][arow] = v.y;
            As[akk + 2][arow] = v.z; As[akk + 3][arow] = v.w;
        } else {
            float2 v = *reinterpret_cast<const float2*>(Ag + k0 + akk);
            As[akk + 0][arow] = v.x; As[akk + 1][arow] = v.y;
        }
        if constexpr (LB == 4) {
            float4 v = *reinterpret_cast<const float4*>(Bg + k0 + bkk);
            Bs[bkk + 0][brow] = v.x; Bs[bkk + 1][brow] = v.y;
            Bs[bkk + 2][brow] = v.z; Bs[bkk + 3][brow] = v.w;
        } else {
            float2 v = *reinterpret_cast<const float2*>(Bg + k0 + bkk);
            Bs[bkk + 0][brow] = v.x; Bs[bkk + 1][brow] = v.y;
        }
        __syncthreads();

#pragma unroll
        for (int kk = 0; kk < KT; kk++) {
            float af[TM], bf[TN];
#pragma unroll
            for (int i = 0; i < TM; i += 4) {
                float4 v = *reinterpret_cast<const float4*>(&As[kk][ty * TM + i]);
                af[i] = v.x; af[i + 1] = v.y; af[i + 2] = v.z; af[i + 3] = v.w;
            }
#pragma unroll
            for (int j = 0; j < TN; j += 4) {
                float4 v = *reinterpret_cast<const float4*>(&Bs[kk][tx * TN + j]);
                bf[j] = v.x; bf[j + 1] = v.y; bf[j + 2] = v.z; bf[j + 3] = v.w;
            }
#pragma unroll
            for (int i = 0; i < TM; i++)
#pragma unroll
                for (int j = 0; j < TN; j++) acc[i][j] += af[i] * bf[j];
        }
        __syncthreads();
    }

#pragma unroll
    for (int i = 0; i < TM; i++) {
        const long m = m0 + ty * TM + i;
#pragma unroll
        for (int j = 0; j < TN; j++) {
            const long n = n0 + tx * TN + j;
            float v = acc[i][j];
            if (Res)   v += Res[m * (long)ldres + n];
            if (bias0) v += bias0[n];
            if (bias1) v += bias1[n];
            C[m * (long)ldc + n] = v;
        }
    }
}

// ---------------------------------------------------------------------------
// Elementwise LSTM cell: gates G[rows,1024] (i,f,g,o chunks of 256), Cin[rows,256]
// ---------------------------------------------------------------------------
__device__ __forceinline__ float sigm(float x) { return 1.f / (1.f + expf(-x)); }

__global__ void lstm_cell_k(const float* __restrict__ G, const float* __restrict__ Cin,
                            float* __restrict__ Hout, float* __restrict__ Cout, int rows)
{
    int idx = blockIdx.x * blockDim.x + threadIdx.x;
    if (idx >= rows * HID) return;
    int n = idx / HID, h = idx % HID;
    const float* g = G + (long)n * G4;
    float gi = g[h], gf = g[HID + h], gg = g[2 * HID + h], go = g[3 * HID + h];
    float c = sigm(gf) * Cin[idx] + sigm(gi) * tanhf(gg);
    Cout[idx] = c;
    Hout[idx] = sigm(go) * tanhf(c);
}

// ---------------------------------------------------------------------------
// DAG level gather: h0/c0 = max over valid parents (NEG fill), 0 if no parents
// ---------------------------------------------------------------------------
__global__ void dag_gather_k(const int* __restrict__ pidx,
                             const unsigned char* __restrict__ pval, int base)
{
    int idx = blockIdx.x * blockDim.x + threadIdx.x;   // [0, KLEV*HID)
    int r = idx / HID, h = idx % HID;
    int n = base + r;
    const int* pi = pidx + (long)n * PPAR;
    float mh = -1e30f, mc = -1e30f;
    bool has = false;
#pragma unroll
    for (int p = 0; p < PPAR; p++) {
        if (pvget(pval, (long)n * PPAR + p)) {
            has = true;
            int q = pi[p];
            mh = fmaxf(mh, g_HD[(long)q * HID + h]);
            mc = fmaxf(mc, g_CD[(long)q * HID + h]);
        }
    }
    g_h0[idx] = has ? mh : 0.f;
    g_c0[idx] = has ? mc : 0.f;
}

// ---------------------------------------------------------------------------
// Root detection + final reduction
// ---------------------------------------------------------------------------
__global__ void zero_children_k() {
    int i = blockIdx.x * blockDim.x + threadIdx.x;
    if (i < NINS) g_children[i] = 0;
}

__global__ void count_children_k(const int* __restrict__ pidx,
                                 const unsigned char* __restrict__ pval) {
    int i = blockIdx.x * blockDim.x + threadIdx.x;
    if (i < NINS * PPAR && pvget(pval, i)) atomicAdd(&g_children[pidx[i]], 1);
}

__global__ void reduce_roots_k() {
    int b = blockIdx.x, h = threadIdx.x;          // 16 blocks x 256
    float m = -1e30f;
    for (int r = 0; r < KLEV; r++) {
        int n = b * KLEV + r;
        if (g_children[n] == 0) m = fmaxf(m, g_HD[(long)n * HID + h]);
    }
    g_partial[b * HID + h] = m;
}

__global__ void final_k(const float* __restrict__ Wlin,
                        const float* __restrict__ blin, float* __restrict__ out) {
    __shared__ float red[HID];
    int h = threadIdx.x;
    float m = -1e30f;
    for (int b = 0; b < 16; b++) m = fmaxf(m, g_partial[b * HID + h]);
    red[h] = m * Wlin[h];
    __syncthreads();
    for (int s = HID / 2; s > 0; s >>= 1) {
        if (h < s) red[h] += red[h + s];
        __syncthreads();
    }
    if (h == 0) out[0] = red[0] + blin[0];
}

// zero both H and C in one launch
__global__ void zero_hc_k(float* H, float* C) {
    int i = blockIdx.x * blockDim.x + threadIdx.x;
    if (i < NINS * HID) { H[i] = 0.f; C[i] = 0.f; }
}

// ---------------------------------------------------------------------------
// Launch
// ---------------------------------------------------------------------------
extern "C" void kernel_launch(void* const* d_in, const int* in_sizes, int n_in,
                              void* d_out, int out_size)
{
    const float*         tokens  = (const float*)d_in[0];
    const int*           pidx    = (const int*)d_in[1];
    const unsigned char* pval    = (const unsigned char*)d_in[2];
    const float*         Wih_tok = (const float*)d_in[3];
    const float*         Whh_tok = (const float*)d_in[4];
    const float*         bih_tok = (const float*)d_in[5];
    const float*         bhh_tok = (const float*)d_in[6];
    const float*         Wih_ins = (const float*)d_in[7];
    const float*         Whh_ins = (const float*)d_in[8];
    const float*         bih_ins = (const float*)d_in[9];
    const float*         bhh_ins = (const float*)d_in[10];
    const float*         Wlin    = (const float*)d_in[11];
    const float*         blin    = (const float*)d_in[12];
    float*               out     = (float*)d_out;

    float *Xg, *X2g, *G, *H, *C, *HD, *CD, *h0, *c0;
    cudaGetSymbolAddress((void**)&Xg,  g_Xg);
    cudaGetSymbolAddress((void**)&X2g, g_X2g);
    cudaGetSymbolAddress((void**)&G,   g_G);
    cudaGetSymbolAddress((void**)&H,   g_H);
    cudaGetSymbolAddress((void**)&C,   g_C);
    cudaGetSymbolAddress((void**)&HD,  g_HD);
    cudaGetSymbolAddress((void**)&CD,  g_CD);
    cudaGetSymbolAddress((void**)&h0,  g_h0);
    cudaGetSymbolAddress((void**)&c0,  g_c0);

    // --- dtype probe for parent_valid (bool vs int32) ---
    detect_pval_k<<<1, 256>>>(pval);

    // --- init token-LSTM state to zero ---
    zero_hc_k<<<(NINS * HID + 255) / 256, 256>>>(H, C);

    // --- big hoisted GEMM: token input gates for ALL steps ---
    // Xg[n*16+t][g] = tokens[n,t,:] @ Wih_tok^T + bih + bhh
    {
        dim3 grid(G4 / 128, (NINS * TTOK) / 128);
        sgemm_k<128, 128, 8, 8><<<grid, 256>>>(
            tokens, EMB, Wih_tok, EMB,
            nullptr, 0, bih_tok, bhh_tok,
            Xg, G4, EMB);
    }

    // --- token-LSTM recurrence: 16 steps ---
    for (int t = 0; t < TTOK; t++) {
        dim3 grid(G4 / 128, NINS / 128);
        sgemm_k<128, 128, 8, 8><<<grid, 256>>>(
            H, HID, Whh_tok, HID,
            Xg + (long)t * G4, TTOK * G4,   // residual = precomputed x-gates for step t
            nullptr, nullptr,
            G, G4, HID);
        lstm_cell_k<<<(NINS * HID + 255) / 256, 256>>>(G, C, H, C, NINS);
    }
    // H now holds ins_embed [2048,256]

    // --- hoisted instruction input gates ---
    {
        dim3 grid(G4 / 128, NINS / 128);
        sgemm_k<128, 128, 8, 8><<<grid, 256>>>(
            H, HID, Wih_ins, HID,
            nullptr, 0, bih_ins, bhh_ins,
            X2g, G4, HID);
    }

    // --- root detection ---
    zero_children_k<<<(NINS + 255) / 256, 256>>>();
    count_children_k<<<(NINS * PPAR + 255) / 256, 256>>>(pidx, pval);

    // --- DAG levels ---
    for (int l = 0; l < LEVELS; l++) {
        int base = l * KLEV;
        dag_gather_k<<<(KLEV * HID + 255) / 256, 256>>>(pidx, pval, base);
        dim3 grid(G4 / 64, KLEV / 64);
        sgemm_k<64, 64, 4, 4><<<grid, 256>>>(
            h0, HID, Whh_ins, HID,
            X2g + (long)base * G4, G4,
            nullptr, nullptr,
            G, G4, HID);
        lstm_cell_k<<<(KLEV * HID + 255) / 256, 256>>>(
            G, c0, HD + (long)base * HID, CD + (long)base * HID, KLEV);
    }

    // --- final: max over roots, linear head ---
    reduce_roots_k<<<16, HID>>>();
    final_k<<<1, HID>>>(Wlin, blin, out);

    (void)in_sizes; (void)n_in; (void)out_size;
}

// round 5
// speedup vs baseline: 1.7615x; 1.7615x over previous
#include <cuda_runtime.h>
#include <math.h>

#define HID    256
#define NINS   2048
#define TTOK   16
#define EMB    512
#define PPAR   8
#define LEVELS 16
#define KLEV   128
#define G4     1024

// ---------------------------------------------------------------------------
// Scratch
// ---------------------------------------------------------------------------
__device__ float g_Xg [NINS * TTOK * G4];   // token input-gates (interleaved cols), row n*16+t
__device__ float g_X2g[NINS * G4];          // instruction input-gates (interleaved)
__device__ float g_Ha [NINS * HID];
__device__ float g_Hb [NINS * HID];
__device__ float g_Ca [NINS * HID];
__device__ float g_Cb [NINS * HID];
__device__ float g_HD [NINS * HID];
__device__ float g_CD [NINS * HID];
__device__ float g_h0 [KLEV * HID];
__device__ float g_c0 [KLEV * HID];
__device__ float g_Wp_tok [G4 * EMB];       // gate-interleaved Wih_tok
__device__ float g_Wph_tok[G4 * HID];       // gate-interleaved Whh_tok
__device__ float g_Wp_ins [G4 * HID];
__device__ float g_Wph_ins[G4 * HID];
__device__ float g_bp_tok[G4];
__device__ float g_bp_ins[G4];
__device__ int   g_children[NINS];
__device__ float g_partial[16 * HID];
__device__ int   g_pval_i32;

// ---------------------------------------------------------------------------
// parent_valid dtype probe (bool vs int32)
// ---------------------------------------------------------------------------
__global__ void detect_pval_k(const unsigned char* __restrict__ pv) {
    __shared__ int cnt;
    if (threadIdx.x == 0) cnt = 0;
    __syncthreads();
    int local = 0;
    for (int i = KLEV * PPAR + threadIdx.x; i < NINS * PPAR; i += blockDim.x)
        if ((i & 3) && pv[i]) local++;
    if (local) atomicAdd(&cnt, local);
    __syncthreads();
    if (threadIdx.x == 0) g_pval_i32 = (cnt == 0) ? 1 : 0;
}
__device__ __forceinline__ bool pvget(const unsigned char* pv, long i) {
    return g_pval_i32 ? (((const int*)pv)[i] != 0) : (pv[i] != 0);
}

// ---------------------------------------------------------------------------
// Weight permutation: out row o = 4u+g  <-  in row g*HID+u.  L = row length.
// ---------------------------------------------------------------------------
__global__ void permute_w_k(const float* __restrict__ W, float* __restrict__ Wp, int L) {
    long i = (long)blockIdx.x * blockDim.x + threadIdx.x;
    if (i >= (long)G4 * L) return;
    int o = (int)(i / L), c = (int)(i % L);
    int g = o & 3, u = o >> 2;
    Wp[i] = W[(long)(g * HID + u) * L + c];
}
__global__ void permute_b_k(const float* __restrict__ b1, const float* __restrict__ b2,
                            float* __restrict__ bp) {
    int o = blockIdx.x * blockDim.x + threadIdx.x;
    if (o < G4) { int g = o & 3, u = o >> 2; bp[o] = b1[g * HID + u] + b2[g * HID + u]; }
}

__global__ void zero2_k(float* a, float* b, int n) {
    int i = blockIdx.x * blockDim.x + threadIdx.x;
    if (i < n) { a[i] = 0.f; b[i] = 0.f; }
}

// ---------------------------------------------------------------------------
// TF32 tensor-core GEMM:  C[M,N] = A[M,K] @ Bw[N,K]^T
// Block 256 thr (8 warps, 4x2), tile 128x128, warp tile 32x64, BK=16, dbl-buffered.
// Smem row stride 20 floats -> conflict-free mma feed; 40960 B static smem.
// Epilogue: FUSE=0 -> Gout = C + Res? + bias?
//           FUSE=1 -> LSTM cell on interleaved gates (i,f,g,o per unit u=ncol/4)
// ---------------------------------------------------------------------------
__device__ __forceinline__ float f2tf(float x) {
    unsigned r; asm("cvt.rna.tf32.f32 %0, %1;" : "=r"(r) : "f"(x));
    return __uint_as_float(r);
}
__device__ __forceinline__ void mma8(float* d, const unsigned* a, const unsigned* b) {
    asm volatile("mma.sync.aligned.m16n8k8.row.col.f32.tf32.tf32.f32 "
        "{%0,%1,%2,%3}, {%4,%5,%6,%7}, {%8,%9}, {%0,%1,%2,%3};\n"
        : "+f"(d[0]), "+f"(d[1]), "+f"(d[2]), "+f"(d[3])
        : "r"(a[0]), "r"(a[1]), "r"(a[2]), "r"(a[3]), "r"(b[0]), "r"(b[1]));
}
__device__ __forceinline__ float sigm(float x) { return 1.f / (1.f + expf(-x)); }

#define SPAD 20

template <bool FUSE>
__global__ void __launch_bounds__(256) gemm_tf32_k(
    const float* __restrict__ A, int lda,
    const float* __restrict__ Bw, int ldb,
    const float* __restrict__ Res, long ldres,
    const float* __restrict__ bias,
    const float* __restrict__ Cin,
    float* __restrict__ Hout, float* __restrict__ Cout,
    float* __restrict__ Gout, int ldc, int K)
{
    __shared__ float As[2][128][SPAD];
    __shared__ float Bs[2][128][SPAD];

    const int tid  = threadIdx.x;
    const int lane = tid & 31;
    const int warp = tid >> 5;
    const int wm   = warp >> 1;            // 0..3
    const int wn   = warp & 1;             // 0..1
    const long m0  = (long)blockIdx.y * 128;
    const long n0  = (long)blockIdx.x * 128;

    float acc[2][8][4];
#pragma unroll
    for (int i = 0; i < 2; i++)
#pragma unroll
        for (int j = 0; j < 8; j++)
#pragma unroll
            for (int k = 0; k < 4; k++) acc[i][j][k] = 0.f;

    const int grow = tid >> 2;             // 0..63
    const int gcol = (tid & 3) * 4;        // 0,4,8,12
    const float* Ag = A  + (m0 + grow) * (long)lda + gcol;
    const float* Bg = Bw + (n0 + grow) * (long)ldb + gcol;

    // preload tile 0
    {
#pragma unroll
        for (int p = 0; p < 2; p++) {
            float4 va = *(const float4*)(Ag + (long)p * 64 * lda);
            float4 vb = *(const float4*)(Bg + (long)p * 64 * ldb);
            int r = grow + p * 64;
            As[0][r][gcol + 0] = f2tf(va.x); As[0][r][gcol + 1] = f2tf(va.y);
            As[0][r][gcol + 2] = f2tf(va.z); As[0][r][gcol + 3] = f2tf(va.w);
            Bs[0][r][gcol + 0] = f2tf(vb.x); Bs[0][r][gcol + 1] = f2tf(vb.y);
            Bs[0][r][gcol + 2] = f2tf(vb.z); Bs[0][r][gcol + 3] = f2tf(vb.w);
        }
    }
    __syncthreads();

    const int nIter = K / 16;
    int buf = 0;
    for (int it = 0; it < nIter; it++) {
        float4 pa[2], pb[2];
        const bool more = (it + 1 < nIter);
        if (more) {
            int k0 = (it + 1) * 16;
#pragma unroll
            for (int p = 0; p < 2; p++) {
                pa[p] = *(const float4*)(Ag + (long)p * 64 * lda + k0);
                pb[p] = *(const float4*)(Bg + (long)p * 64 * ldb + k0);
            }
        }
        // compute on smem[buf]
#pragma unroll
        for (int kk = 0; kk < 16; kk += 8) {
            unsigned a[2][4], b[8][2];
#pragma unroll
            for (int mf = 0; mf < 2; mf++) {
                int r = wm * 32 + mf * 16 + (lane >> 2);
                int c = kk + (lane & 3);
                a[mf][0] = __float_as_uint(As[buf][r][c]);
                a[mf][1] = __float_as_uint(As[buf][r + 8][c]);
                a[mf][2] = __float_as_uint(As[buf][r][c + 4]);
                a[mf][3] = __float_as_uint(As[buf][r + 8][c + 4]);
            }
#pragma unroll
            for (int nf = 0; nf < 8; nf++) {
                int r = wn * 64 + nf * 8 + (lane >> 2);
                int c = kk + (lane & 3);
                b[nf][0] = __float_as_uint(Bs[buf][r][c]);
                b[nf][1] = __float_as_uint(Bs[buf][r][c + 4]);
            }
#pragma unroll
            for (int mf = 0; mf < 2; mf++)
#pragma unroll
                for (int nf = 0; nf < 8; nf++) mma8(acc[mf][nf], a[mf], b[nf]);
        }
        if (more) {
            int nb = buf ^ 1;
#pragma unroll
            for (int p = 0; p < 2; p++) {
                int r = grow + p * 64;
                As[nb][r][gcol + 0] = f2tf(pa[p].x); As[nb][r][gcol + 1] = f2tf(pa[p].y);
                As[nb][r][gcol + 2] = f2tf(pa[p].z); As[nb][r][gcol + 3] = f2tf(pa[p].w);
                Bs[nb][r][gcol + 0] = f2tf(pb[p].x); Bs[nb][r][gcol + 1] = f2tf(pb[p].y);
                Bs[nb][r][gcol + 2] = f2tf(pb[p].z); Bs[nb][r][gcol + 3] = f2tf(pb[p].w);
            }
            __syncthreads();
            buf = nb;
        }
    }

    // ---------------- epilogue ----------------
#pragma unroll
    for (int mf = 0; mf < 2; mf++) {
        const long rA = m0 + wm * 32 + mf * 16 + (lane >> 2);
        const long rB = rA + 8;
#pragma unroll
        for (int nf = 0; nf < 8; nf++) {
            const int ncol = (int)n0 + wn * 64 + nf * 8 + 2 * (lane & 3);
            float x0 = acc[mf][nf][0], x1 = acc[mf][nf][1];
            float x2 = acc[mf][nf][2], x3 = acc[mf][nf][3];
            if (Res) {
                x0 += Res[rA * ldres + ncol];     x1 += Res[rA * ldres + ncol + 1];
                x2 += Res[rB * ldres + ncol];     x3 += Res[rB * ldres + ncol + 1];
            }
            if (!FUSE) {
                if (bias) {
                    float b0 = bias[ncol], b1 = bias[ncol + 1];
                    x0 += b0; x1 += b1; x2 += b0; x3 += b1;
                }
                *(float2*)(Gout + rA * ldc + ncol) = make_float2(x0, x1);
                *(float2*)(Gout + rB * ldc + ncol) = make_float2(x2, x3);
            } else {
                // even lane (lane&1)==0 holds (i,f); odd holds (g,o); same unit
                float y0 = __shfl_xor_sync(0xffffffffu, x0, 1);
                float y1 = __shfl_xor_sync(0xffffffffu, x1, 1);
                float y2 = __shfl_xor_sync(0xffffffffu, x2, 1);
                float y3 = __shfl_xor_sync(0xffffffffu, x3, 1);
                if ((lane & 1) == 0) {
                    int u = ncol >> 2;   // ncol % 4 == 0 here
                    float cA = sigm(x1) * Cin[rA * HID + u] + sigm(x0) * tanhf(y0);
                    float hA = sigm(y1) * tanhf(cA);
                    float cB = sigm(x3) * Cin[rB * HID + u] + sigm(x2) * tanhf(y2);
                    float hB = sigm(y3) * tanhf(cB);
                    Cout[rA * HID + u] = cA;  Hout[rA * HID + u] = hA;
                    Cout[rB * HID + u] = cB;  Hout[rB * HID + u] = hB;
                }
            }
        }
    }
}

// ---------------------------------------------------------------------------
// DAG gather, roots, final
// ---------------------------------------------------------------------------
__global__ void dag_gather_k(const int* __restrict__ pidx,
                             const unsigned char* __restrict__ pval, int base)
{
    int idx = blockIdx.x * blockDim.x + threadIdx.x;   // [0, KLEV*HID)
    int r = idx / HID, h = idx % HID;
    int n = base + r;
    const int* pi = pidx + (long)n * PPAR;
    float mh = -1e30f, mc = -1e30f;
    bool has = false;
#pragma unroll
    for (int p = 0; p < PPAR; p++) {
        if (pvget(pval, (long)n * PPAR + p)) {
            has = true;
            int q = pi[p];
            mh = fmaxf(mh, g_HD[(long)q * HID + h]);
            mc = fmaxf(mc, g_CD[(long)q * HID + h]);
        }
    }
    g_h0[idx] = has ? mh : 0.f;
    g_c0[idx] = has ? mc : 0.f;
}

__global__ void zero_children_k() {
    int i = blockIdx.x * blockDim.x + threadIdx.x;
    if (i < NINS) g_children[i] = 0;
}
__global__ void count_children_k(const int* __restrict__ pidx,
                                 const unsigned char* __restrict__ pval) {
    int i = blockIdx.x * blockDim.x + threadIdx.x;
    if (i < NINS * PPAR && pvget(pval, i)) atomicAdd(&g_children[pidx[i]], 1);
}
__global__ void reduce_roots_k() {
    int b = blockIdx.x, h = threadIdx.x;
    float m = -1e30f;
    for (int r = 0; r < KLEV; r++) {
        int n = b * KLEV + r;
        if (g_children[n] == 0) m = fmaxf(m, g_HD[(long)n * HID + h]);
    }
    g_partial[b * HID + h] = m;
}
__global__ void final_k(const float* __restrict__ Wlin,
                        const float* __restrict__ blin, float* __restrict__ out) {
    __shared__ float red[HID];
    int h = threadIdx.x;
    float m = -1e30f;
    for (int b = 0; b < 16; b++) m = fmaxf(m, g_partial[b * HID + h]);
    red[h] = m * Wlin[h];
    __syncthreads();
    for (int s = HID / 2; s > 0; s >>= 1) {
        if (h < s) red[h] += red[h + s];
        __syncthreads();
    }
    if (h == 0) out[0] = red[0] + blin[0];
}

// ---------------------------------------------------------------------------
// Launch
// ---------------------------------------------------------------------------
extern "C" void kernel_launch(void* const* d_in, const int* in_sizes, int n_in,
                              void* d_out, int out_size)
{
    const float*         tokens  = (const float*)d_in[0];
    const int*           pidx    = (const int*)d_in[1];
    const unsigned char* pval    = (const unsigned char*)d_in[2];
    const float*         Wih_tok = (const float*)d_in[3];
    const float*         Whh_tok = (const float*)d_in[4];
    const float*         bih_tok = (const float*)d_in[5];
    const float*         bhh_tok = (const float*)d_in[6];
    const float*         Wih_ins = (const float*)d_in[7];
    const float*         Whh_ins = (const float*)d_in[8];
    const float*         bih_ins = (const float*)d_in[9];
    const float*         bhh_ins = (const float*)d_in[10];
    const float*         Wlin    = (const float*)d_in[11];
    const float*         blin    = (const float*)d_in[12];
    float*               out     = (float*)d_out;

    float *Xg, *X2g, *Ha, *Hb, *Ca, *Cb, *HD, *CD, *h0, *c0;
    float *Wp_tok, *Wph_tok, *Wp_ins, *Wph_ins, *bp_tok, *bp_ins;
    cudaGetSymbolAddress((void**)&Xg,      g_Xg);
    cudaGetSymbolAddress((void**)&X2g,     g_X2g);
    cudaGetSymbolAddress((void**)&Ha,      g_Ha);
    cudaGetSymbolAddress((void**)&Hb,      g_Hb);
    cudaGetSymbolAddress((void**)&Ca,      g_Ca);
    cudaGetSymbolAddress((void**)&Cb,      g_Cb);
    cudaGetSymbolAddress((void**)&HD,      g_HD);
    cudaGetSymbolAddress((void**)&CD,      g_CD);
    cudaGetSymbolAddress((void**)&h0,      g_h0);
    cudaGetSymbolAddress((void**)&c0,      g_c0);
    cudaGetSymbolAddress((void**)&Wp_tok,  g_Wp_tok);
    cudaGetSymbolAddress((void**)&Wph_tok, g_Wph_tok);
    cudaGetSymbolAddress((void**)&Wp_ins,  g_Wp_ins);
    cudaGetSymbolAddress((void**)&Wph_ins, g_Wph_ins);
    cudaGetSymbolAddress((void**)&bp_tok,  g_bp_tok);
    cudaGetSymbolAddress((void**)&bp_ins,  g_bp_ins);

    detect_pval_k<<<1, 256>>>(pval);

    // permutations (gate-interleave)
    permute_w_k<<<((long)G4 * EMB + 255) / 256, 256>>>(Wih_tok, Wp_tok, EMB);
    permute_w_k<<<((long)G4 * HID + 255) / 256, 256>>>(Whh_tok, Wph_tok, HID);
    permute_w_k<<<((long)G4 * HID + 255) / 256, 256>>>(Wih_ins, Wp_ins, HID);
    permute_w_k<<<((long)G4 * HID + 255) / 256, 256>>>(Whh_ins, Wph_ins, HID);
    permute_b_k<<<4, 256>>>(bih_tok, bhh_tok, bp_tok);
    permute_b_k<<<4, 256>>>(bih_ins, bhh_ins, bp_ins);

    zero2_k<<<(NINS * HID + 255) / 256, 256>>>(Ha, Ca, NINS * HID);

    // big hoisted GEMM: Xg = tokens @ Wp_tok^T + bp (interleaved gate cols)
    gemm_tf32_k<false><<<dim3(G4 / 128, (NINS * TTOK) / 128), 256>>>(
        tokens, EMB, Wp_tok, EMB, nullptr, 0, bp_tok,
        nullptr, nullptr, nullptr, Xg, G4, EMB);

    // token-LSTM recurrence (fused cell epilogue, ping-pong H/C)
    float* Hp = Ha; float* Cp = Ca; float* Hn = Hb; float* Cn = Cb;
    for (int t = 0; t < TTOK; t++) {
        gemm_tf32_k<true><<<dim3(G4 / 128, NINS / 128), 256>>>(
            Hp, HID, Wph_tok, HID, Xg + (long)t * G4, (long)TTOK * G4, nullptr,
            Cp, Hn, Cn, nullptr, 0, HID);
        float* tmp;
        tmp = Hp; Hp = Hn; Hn = tmp;
        tmp = Cp; Cp = Cn; Cn = tmp;
    }
    // final ins_embed in Hp (= Ha after 16 steps)

    // hoisted instruction input gates: X2g = ins_embed @ Wp_ins^T + bp_ins
    gemm_tf32_k<false><<<dim3(G4 / 128, NINS / 128), 256>>>(
        Hp, HID, Wp_ins, HID, nullptr, 0, bp_ins,
        nullptr, nullptr, nullptr, X2g, G4, HID);

    // root detection
    zero_children_k<<<(NINS + 255) / 256, 256>>>();
    count_children_k<<<(NINS * PPAR + 255) / 256, 256>>>(pidx, pval);

    // DAG levels (gather + fused GEMM-cell)
    for (int l = 0; l < LEVELS; l++) {
        int base = l * KLEV;
        dag_gather_k<<<(KLEV * HID + 255) / 256, 256>>>(pidx, pval, base);
        gemm_tf32_k<true><<<dim3(G4 / 128, 1), 256>>>(
            h0, HID, Wph_ins, HID, X2g + (long)base * G4, G4, nullptr,
            c0, HD + (long)base * HID, CD + (long)base * HID, nullptr, 0, HID);
    }

    reduce_roots_k<<<16, HID>>>();
    final_k<<<1, HID>>>(Wlin, blin, out);

    (void)in_sizes; (void)n_in; (void)out_size;
}

// round 13
// speedup vs baseline: 2.0133x; 1.1430x over previous
#include <cuda_runtime.h>
#include <math.h>

#define HID    256
#define NINS   2048
#define TTOK   16
#define EMB    512
#define PPAR   8
#define LEVELS 16
#define KLEV   128
#define G4     1024

#define NB_REC 128     // persistent recurrence blocks (16 m-blocks x 8 n-blocks)
#define NB_DAG 32      // persistent DAG blocks (2 m-blocks x 16 n-blocks)

// ---------------------------------------------------------------------------
// Scratch
// ---------------------------------------------------------------------------
__device__ float g_Xg [NINS * TTOK * G4];
__device__ float g_X2g[NINS * G4];
__device__ float g_Ha [NINS * HID];
__device__ float g_Hb [NINS * HID];
__device__ float g_Ca [NINS * HID];
__device__ float g_Cb [NINS * HID];
__device__ float g_HD [NINS * HID];
__device__ float g_CD [NINS * HID];
__device__ float g_h0 [KLEV * HID];
__device__ float g_c0 [KLEV * HID];
__device__ float g_Wp_tok [G4 * EMB];
__device__ float g_Wph_tok[G4 * HID];
__device__ float g_Wp_ins [G4 * HID];
__device__ float g_Wph_ins[G4 * HID];
__device__ float g_bp_tok[G4];
__device__ float g_bp_ins[G4];
__device__ int   g_children[NINS];
__device__ float g_partial[16 * HID];
__device__ int   g_pval_i32;
__device__ int   g_cnt1 = 0, g_gen1 = 0;   // recurrence barrier
__device__ int   g_cnt2 = 0, g_gen2 = 0;   // DAG barrier

// ---------------------------------------------------------------------------
// software grid barrier (blocks co-resident by construction)
// ---------------------------------------------------------------------------
__device__ __forceinline__ void gridbar(int* cnt, int* gen, int nb) {
    __syncthreads();
    if (threadIdx.x == 0) {
        int my = *(volatile int*)gen;
        __threadfence();
        if (atomicAdd(cnt, 1) == nb - 1) {
            atomicExch(cnt, 0);
            __threadfence();
            atomicAdd(gen, 1);
        } else {
            while (*(volatile int*)gen == my) { }
        }
        __threadfence();
    }
    __syncthreads();
}

// ---------------------------------------------------------------------------
// parent_valid dtype probe (bool vs int32)
// ---------------------------------------------------------------------------
__global__ void detect_pval_k(const unsigned char* __restrict__ pv) {
    __shared__ int cnt;
    if (threadIdx.x == 0) cnt = 0;
    __syncthreads();
    int local = 0;
    for (int i = KLEV * PPAR + threadIdx.x; i < NINS * PPAR; i += blockDim.x)
        if ((i & 3) && pv[i]) local++;
    if (local) atomicAdd(&cnt, local);
    __syncthreads();
    if (threadIdx.x == 0) g_pval_i32 = (cnt == 0) ? 1 : 0;
}
__device__ __forceinline__ bool pvget(const unsigned char* pv, long i) {
    return g_pval_i32 ? (((const int*)pv)[i] != 0) : (pv[i] != 0);
}

// ---------------------------------------------------------------------------
// Fused setup: gate-interleave all weights (row o=4u+g <- g*HID+u), biases,
// and zero-init Ha/Ca.
// ---------------------------------------------------------------------------
__global__ void setup_k(const float* __restrict__ Wih_tok, const float* __restrict__ Whh_tok,
                        const float* __restrict__ Wih_ins, const float* __restrict__ Whh_ins,
                        const float* __restrict__ bih_tok, const float* __restrict__ bhh_tok,
                        const float* __restrict__ bih_ins, const float* __restrict__ bhh_ins)
{
    const long S0 = (long)G4 * EMB;
    const long S1 = S0 + (long)G4 * HID;
    const long S2 = S1 + (long)G4 * HID;
    const long S3 = S2 + (long)G4 * HID;
    const long S4 = S3 + 2 * G4;
    const long S5 = S4 + (long)NINS * HID;
    for (long i = (long)blockIdx.x * blockDim.x + threadIdx.x; i < S5;
         i += (long)gridDim.x * blockDim.x) {
        if (i < S0) {
            long j = i; int o = (int)(j / EMB), c = (int)(j % EMB);
            g_Wp_tok[j] = Wih_tok[(long)((o & 3) * HID + (o >> 2)) * EMB + c];
        } else if (i < S1) {
            long j = i - S0; int o = (int)(j / HID), c = (int)(j % HID);
            g_Wph_tok[j] = Whh_tok[(long)((o & 3) * HID + (o >> 2)) * HID + c];
        } else if (i < S2) {
            long j = i - S1; int o = (int)(j / HID), c = (int)(j % HID);
            g_Wp_ins[j] = Wih_ins[(long)((o & 3) * HID + (o >> 2)) * HID + c];
        } else if (i < S3) {
            long j = i - S2; int o = (int)(j / HID), c = (int)(j % HID);
            g_Wph_ins[j] = Whh_ins[(long)((o & 3) * HID + (o >> 2)) * HID + c];
        } else if (i < S4) {
            long j = i - S3;
            if (j < G4) { int o = (int)j;      g_bp_tok[o] = bih_tok[(o & 3) * HID + (o >> 2)] + bhh_tok[(o & 3) * HID + (o >> 2)]; }
            else        { int o = (int)j - G4; g_bp_ins[o] = bih_ins[(o & 3) * HID + (o >> 2)] + bhh_ins[(o & 3) * HID + (o >> 2)]; }
        } else {
            long j = i - S4; g_Ha[j] = 0.f; g_Ca[j] = 0.f;
        }
    }
}

// ---------------------------------------------------------------------------
// TF32 mma helpers
// ---------------------------------------------------------------------------
__device__ __forceinline__ float f2tf(float x) {
    unsigned r; asm("cvt.rna.tf32.f32 %0, %1;" : "=r"(r) : "f"(x));
    return __uint_as_float(r);
}
__device__ __forceinline__ void mma8(float* d, const unsigned* a, const unsigned* b) {
    asm volatile("mma.sync.aligned.m16n8k8.row.col.f32.tf32.tf32.f32 "
        "{%0,%1,%2,%3}, {%4,%5,%6,%7}, {%8,%9}, {%0,%1,%2,%3};\n"
        : "+f"(d[0]), "+f"(d[1]), "+f"(d[2]), "+f"(d[3])
        : "r"(a[0]), "r"(a[1]), "r"(a[2]), "r"(a[3]), "r"(b[0]), "r"(b[1]));
}
__device__ __forceinline__ float sigm(float x) { return 1.f / (1.f + expf(-x)); }

#define SPAD 20

// ---------------------------------------------------------------------------
// 128x128 GEMM tile body (device fn).  C = A[M,K] @ Bw[N,K]^T (+Res)(+bias)
// FUSE=1: LSTM cell epilogue on gate-interleaved columns.
// ---------------------------------------------------------------------------
template <bool FUSE>
__device__ __forceinline__ void gemm_tile_128(
    float (&As)[2][128][SPAD], float (&Bs)[2][128][SPAD],
    int bx, int by,
    const float* __restrict__ A, int lda,
    const float* __restrict__ Bw, int ldb,
    const float* __restrict__ Res, long ldres,
    const float* __restrict__ bias,
    const float* __restrict__ Cin,
    float* __restrict__ Hout, float* __restrict__ Cout,
    float* __restrict__ Gout, int ldc, int K)
{
    const int tid  = threadIdx.x;
    const int lane = tid & 31;
    const int warp = tid >> 5;
    const int wm   = warp >> 1;            // 0..3
    const int wn   = warp & 1;             // 0..1
    const long m0  = (long)by * 128;
    const long n0  = (long)bx * 128;

    float acc[2][8][4];
#pragma unroll
    for (int i = 0; i < 2; i++)
#pragma unroll
        for (int j = 0; j < 8; j++)
#pragma unroll
            for (int k = 0; k < 4; k++) acc[i][j][k] = 0.f;

    const int grow = tid >> 2;             // 0..63
    const int gcol = (tid & 3) * 4;        // 0,4,8,12
    const float* Ag = A  + (m0 + grow) * (long)lda + gcol;
    const float* Bg = Bw + (n0 + grow) * (long)ldb + gcol;

#pragma unroll
    for (int p = 0; p < 2; p++) {
        float4 va = *(const float4*)(Ag + (long)p * 64 * lda);
        float4 vb = *(const float4*)(Bg + (long)p * 64 * ldb);
        int r = grow + p * 64;
        As[0][r][gcol + 0] = f2tf(va.x); As[0][r][gcol + 1] = f2tf(va.y);
        As[0][r][gcol + 2] = f2tf(va.z); As[0][r][gcol + 3] = f2tf(va.w);
        Bs[0][r][gcol + 0] = f2tf(vb.x); Bs[0][r][gcol + 1] = f2tf(vb.y);
        Bs[0][r][gcol + 2] = f2tf(vb.z); Bs[0][r][gcol + 3] = f2tf(vb.w);
    }
    __syncthreads();

    const int nIter = K / 16;
    int buf = 0;
    for (int it = 0; it < nIter; it++) {
        float4 pa[2], pb[2];
        const bool more = (it + 1 < nIter);
        if (more) {
            int k0 = (it + 1) * 16;
#pragma unroll
            for (int p = 0; p < 2; p++) {
                pa[p] = *(const float4*)(Ag + (long)p * 64 * lda + k0);
                pb[p] = *(const float4*)(Bg + (long)p * 64 * ldb + k0);
            }
        }
#pragma unroll
        for (int kk = 0; kk < 16; kk += 8) {
            unsigned a[2][4], b[8][2];
#pragma unroll
            for (int mf = 0; mf < 2; mf++) {
                int r = wm * 32 + mf * 16 + (lane >> 2);
                int c = kk + (lane & 3);
                a[mf][0] = __float_as_uint(As[buf][r][c]);
                a[mf][1] = __float_as_uint(As[buf][r + 8][c]);
                a[mf][2] = __float_as_uint(As[buf][r][c + 4]);
                a[mf][3] = __float_as_uint(As[buf][r + 8][c + 4]);
            }
#pragma unroll
            for (int nf = 0; nf < 8; nf++) {
                int r = wn * 64 + nf * 8 + (lane >> 2);
                int c = kk + (lane & 3);
                b[nf][0] = __float_as_uint(Bs[buf][r][c]);
                b[nf][1] = __float_as_uint(Bs[buf][r][c + 4]);
            }
#pragma unroll
            for (int mf = 0; mf < 2; mf++)
#pragma unroll
                for (int nf = 0; nf < 8; nf++) mma8(acc[mf][nf], a[mf], b[nf]);
        }
        if (more) {
            int nb = buf ^ 1;
#pragma unroll
            for (int p = 0; p < 2; p++) {
                int r = grow + p * 64;
                As[nb][r][gcol + 0] = f2tf(pa[p].x); As[nb][r][gcol + 1] = f2tf(pa[p].y);
                As[nb][r][gcol + 2] = f2tf(pa[p].z); As[nb][r][gcol + 3] = f2tf(pa[p].w);
                Bs[nb][r][gcol + 0] = f2tf(pb[p].x); Bs[nb][r][gcol + 1] = f2tf(pb[p].y);
                Bs[nb][r][gcol + 2] = f2tf(pb[p].z); Bs[nb][r][gcol + 3] = f2tf(pb[p].w);
            }
            __syncthreads();
            buf = nb;
        }
    }

#pragma unroll
    for (int mf = 0; mf < 2; mf++) {
        const long rA = m0 + wm * 32 + mf * 16 + (lane >> 2);
        const long rB = rA + 8;
#pragma unroll
        for (int nf = 0; nf < 8; nf++) {
            const int ncol = (int)n0 + wn * 64 + nf * 8 + 2 * (lane & 3);
            float x0 = acc[mf][nf][0], x1 = acc[mf][nf][1];
            float x2 = acc[mf][nf][2], x3 = acc[mf][nf][3];
            if (Res) {
                x0 += Res[rA * ldres + ncol];     x1 += Res[rA * ldres + ncol + 1];
                x2 += Res[rB * ldres + ncol];     x3 += Res[rB * ldres + ncol + 1];
            }
            if (!FUSE) {
                if (bias) {
                    float b0 = bias[ncol], b1 = bias[ncol + 1];
                    x0 += b0; x1 += b1; x2 += b0; x3 += b1;
                }
                *(float2*)(Gout + rA * ldc + ncol) = make_float2(x0, x1);
                *(float2*)(Gout + rB * ldc + ncol) = make_float2(x2, x3);
            } else {
                float y0 = __shfl_xor_sync(0xffffffffu, x0, 1);
                float y1 = __shfl_xor_sync(0xffffffffu, x1, 1);
                float y2 = __shfl_xor_sync(0xffffffffu, x2, 1);
                float y3 = __shfl_xor_sync(0xffffffffu, x3, 1);
                if ((lane & 1) == 0) {
                    int u = ncol >> 2;
                    float cA = sigm(x1) * Cin[rA * HID + u] + sigm(x0) * tanhf(y0);
                    float hA = sigm(y1) * tanhf(cA);
                    float cB = sigm(x3) * Cin[rB * HID + u] + sigm(x2) * tanhf(y2);
                    float hB = sigm(y3) * tanhf(cB);
                    Cout[rA * HID + u] = cA;  Hout[rA * HID + u] = hA;
                    Cout[rB * HID + u] = cB;  Hout[rB * HID + u] = hB;
                }
            }
        }
    }
}

// standalone wrapper (big hoisted GEMM)
__global__ void __launch_bounds__(256) gemm_plain_k(
    const float* __restrict__ A, int lda, const float* __restrict__ Bw, int ldb,
    const float* __restrict__ bias, float* __restrict__ Gout, int ldc, int K)
{
    __shared__ float As[2][128][SPAD];
    __shared__ float Bs[2][128][SPAD];
    gemm_tile_128<false>(As, Bs, blockIdx.x, blockIdx.y,
                         A, lda, Bw, ldb, nullptr, 0, bias,
                         nullptr, nullptr, nullptr, Gout, ldc, K);
}

// ---------------------------------------------------------------------------
// Persistent recurrence: 16 fused GEMM-cell steps + final X2g GEMM. 128 blocks.
// ---------------------------------------------------------------------------
__global__ void __launch_bounds__(256) recur_persist_k(float* dummy)
{
    __shared__ float As[2][128][SPAD];
    __shared__ float Bs[2][128][SPAD];
    const int bid = blockIdx.x;
    const int bx = bid & 7, by = bid >> 3;

    float* Hp = g_Ha; float* Cp = g_Ca; float* Hn = g_Hb; float* Cn = g_Cb;
    for (int t = 0; t < TTOK; t++) {
        gemm_tile_128<true>(As, Bs, bx, by,
            Hp, HID, g_Wph_tok, HID,
            g_Xg + (long)t * G4, (long)TTOK * G4, nullptr,
            Cp, Hn, Cn, nullptr, 0, HID);
        __threadfence();
        gridbar(&g_cnt1, &g_gen1, NB_REC);
        float* tmp;
        tmp = Hp; Hp = Hn; Hn = tmp;
        tmp = Cp; Cp = Cn; Cn = tmp;
    }
    // X2g = ins_embed @ Wp_ins^T + bp_ins
    gemm_tile_128<false>(As, Bs, bx, by,
        Hp, HID, g_Wp_ins, HID, nullptr, 0, g_bp_ins,
        nullptr, nullptr, nullptr, g_X2g, G4, HID);
    (void)dummy;
}

// ---------------------------------------------------------------------------
// Persistent DAG: children-count + 16 levels (gather | 64x64 fused GEMM-cell)
// + root-max + final linear.  32 blocks (2 m x 16 n).
// ---------------------------------------------------------------------------
__global__ void __launch_bounds__(256) dag_persist_k(
    const int* __restrict__ pidx, const unsigned char* __restrict__ pval,
    const float* __restrict__ Wlin, const float* __restrict__ blin,
    float* __restrict__ out)
{
    __shared__ float As[64][36];
    __shared__ float Bs[64][36];
    __shared__ float red[HID];

    const int tid  = threadIdx.x;
    const int bid  = blockIdx.x;
    const int lane = tid & 31;
    const int warp = tid >> 5;
    const int wm   = warp >> 2;        // 0..1
    const int wn   = warp & 3;         // 0..3
    const int by   = bid >> 4;         // 0..1  (m-block)
    const int bx   = bid & 15;         // 0..15 (n-block)
    const int gid  = bid * 256 + tid;  // 0..8191

    // children count
    for (int i = gid; i < NINS; i += NB_DAG * 256) g_children[i] = 0;
    gridbar(&g_cnt2, &g_gen2, NB_DAG);
    for (int i = gid; i < NINS * PPAR; i += NB_DAG * 256)
        if (pvget(pval, i)) atomicAdd(&g_children[pidx[i]], 1);
    // (visibility of counts ensured by the many barriers before the root reduce)

    for (int l = 0; l < LEVELS; l++) {
        const int base = l * KLEV;
        // ---- gather parents ----
        for (int idx = gid; idx < KLEV * HID; idx += NB_DAG * 256) {
            int r = idx >> 8, h = idx & 255;
            int n = base + r;
            const int* pi = pidx + (long)n * PPAR;
            float mh = -1e30f, mc = -1e30f;
            bool has = false;
#pragma unroll
            for (int p = 0; p < PPAR; p++) {
                if (pvget(pval, (long)n * PPAR + p)) {
                    has = true;
                    int q = pi[p];
                    mh = fmaxf(mh, g_HD[(long)q * HID + h]);
                    mc = fmaxf(mc, g_CD[(long)q * HID + h]);
                }
            }
            g_h0[idx] = has ? mh : 0.f;
            g_c0[idx] = has ? mc : 0.f;
        }
        __threadfence();
        gridbar(&g_cnt2, &g_gen2, NB_DAG);

        // ---- 64x64 fused GEMM-cell:  gates = h0 @ Wph_ins^T + X2g[level] ----
        const int m0 = by * 64, n0 = bx * 64;
        float acc[2][2][4];
#pragma unroll
        for (int i = 0; i < 2; i++)
#pragma unroll
            for (int j = 0; j < 2; j++)
#pragma unroll
                for (int k = 0; k < 4; k++) acc[i][j][k] = 0.f;

        const int lrow = tid >> 3;        // 0..31
        const int lcol = (tid & 7) * 4;   // 0..28
        for (int k0 = 0; k0 < HID; k0 += 32) {
            __syncthreads();
#pragma unroll
            for (int p = 0; p < 2; p++) {
                int r = lrow + p * 32;
                float4 va = *(const float4*)(g_h0 + (long)(m0 + r) * HID + k0 + lcol);
                float4 vb = *(const float4*)(g_Wph_ins + (long)(n0 + r) * HID + k0 + lcol);
                As[r][lcol + 0] = f2tf(va.x); As[r][lcol + 1] = f2tf(va.y);
                As[r][lcol + 2] = f2tf(va.z); As[r][lcol + 3] = f2tf(va.w);
                Bs[r][lcol + 0] = f2tf(vb.x); Bs[r][lcol + 1] = f2tf(vb.y);
                Bs[r][lcol + 2] = f2tf(vb.z); Bs[r][lcol + 3] = f2tf(vb.w);
            }
            __syncthreads();
#pragma unroll
            for (int kk = 0; kk < 32; kk += 8) {
                unsigned a[2][4], b[2][2];
#pragma unroll
                for (int mf = 0; mf < 2; mf++) {
                    int r = wm * 32 + mf * 16 + (lane >> 2);
                    int c = kk + (lane & 3);
                    a[mf][0] = __float_as_uint(As[r][c]);
                    a[mf][1] = __float_as_uint(As[r + 8][c]);
                    a[mf][2] = __float_as_uint(As[r][c + 4]);
                    a[mf][3] = __float_as_uint(As[r + 8][c + 4]);
                }
#pragma unroll
                for (int nf = 0; nf < 2; nf++) {
                    int r = wn * 16 + nf * 8 + (lane >> 2);
                    int c = kk + (lane & 3);
                    b[nf][0] = __float_as_uint(Bs[r][c]);
                    b[nf][1] = __float_as_uint(Bs[r][c + 4]);
                }
#pragma unroll
                for (int mf = 0; mf < 2; mf++)
#pragma unroll
                    for (int nf = 0; nf < 2; nf++) mma8(acc[mf][nf], a[mf], b[nf]);
            }
        }

        // cell epilogue
#pragma unroll
        for (int mf = 0; mf < 2; mf++) {
            const int rA = m0 + wm * 32 + mf * 16 + (lane >> 2);
            const int rB = rA + 8;
#pragma unroll
            for (int nf = 0; nf < 2; nf++) {
                const int ncol = n0 + wn * 16 + nf * 8 + 2 * (lane & 3);
                const float* Res = g_X2g + (long)base * G4;
                float x0 = acc[mf][nf][0] + Res[(long)rA * G4 + ncol];
                float x1 = acc[mf][nf][1] + Res[(long)rA * G4 + ncol + 1];
                float x2 = acc[mf][nf][2] + Res[(long)rB * G4 + ncol];
                float x3 = acc[mf][nf][3] + Res[(long)rB * G4 + ncol + 1];
                float y0 = __shfl_xor_sync(0xffffffffu, x0, 1);
                float y1 = __shfl_xor_sync(0xffffffffu, x1, 1);
                float y2 = __shfl_xor_sync(0xffffffffu, x2, 1);
                float y3 = __shfl_xor_sync(0xffffffffu, x3, 1);
                if ((lane & 1) == 0) {
                    int u = ncol >> 2;
                    float cA = sigm(x1) * g_c0[(long)rA * HID + u] + sigm(x0) * tanhf(y0);
                    float hA = sigm(y1) * tanhf(cA);
                    float cB = sigm(x3) * g_c0[(long)rB * HID + u] + sigm(x2) * tanhf(y2);
                    float hB = sigm(y3) * tanhf(cB);
                    g_CD[(long)(base + rA) * HID + u] = cA;
                    g_HD[(long)(base + rA) * HID + u] = hA;
                    g_CD[(long)(base + rB) * HID + u] = cB;
                    g_HD[(long)(base + rB) * HID + u] = hB;
                }
            }
        }
        __threadfence();
        gridbar(&g_cnt2, &g_gen2, NB_DAG);
    }

    // root-max partials (blocks 0..15)
    if (bid < 16) {
        float m = -1e30f;
        for (int r = 0; r < KLEV; r++) {
            int n = bid * KLEV + r;
            if (g_children[n] == 0) m = fmaxf(m, g_HD[(long)n * HID + tid]);
        }
        g_partial[bid * HID + tid] = m;
    }
    __threadfence();
    gridbar(&g_cnt2, &g_gen2, NB_DAG);

    // final linear (block 0)
    if (bid == 0) {
        float m = -1e30f;
        for (int b = 0; b < 16; b++) m = fmaxf(m, g_partial[b * HID + tid]);
        red[tid] = m * Wlin[tid];
        __syncthreads();
        for (int s = HID / 2; s > 0; s >>= 1) {
            if (tid < s) red[tid] += red[tid + s];
            __syncthreads();
        }
        if (tid == 0) out[0] = red[0] + blin[0];
    }
}

// ---------------------------------------------------------------------------
// Launch
// ---------------------------------------------------------------------------
extern "C" void kernel_launch(void* const* d_in, const int* in_sizes, int n_in,
                              void* d_out, int out_size)
{
    const float*         tokens  = (const float*)d_in[0];
    const int*           pidx    = (const int*)d_in[1];
    const unsigned char* pval    = (const unsigned char*)d_in[2];
    const float*         Wih_tok = (const float*)d_in[3];
    const float*         Whh_tok = (const float*)d_in[4];
    const float*         bih_tok = (const float*)d_in[5];
    const float*         bhh_tok = (const float*)d_in[6];
    const float*         Wih_ins = (const float*)d_in[7];
    const float*         Whh_ins = (const float*)d_in[8];
    const float*         bih_ins = (const float*)d_in[9];
    const float*         bhh_ins = (const float*)d_in[10];
    const float*         Wlin    = (const float*)d_in[11];
    const float*         blin    = (const float*)d_in[12];
    float*               out     = (float*)d_out;

    float *Xg, *Wp_tok, *bp_tok;
    cudaGetSymbolAddress((void**)&Xg,     g_Xg);
    cudaGetSymbolAddress((void**)&Wp_tok, g_Wp_tok);
    cudaGetSymbolAddress((void**)&bp_tok, g_bp_tok);

    detect_pval_k<<<1, 256>>>(pval);
    setup_k<<<1184, 256>>>(Wih_tok, Whh_tok, Wih_ins, Whh_ins,
                           bih_tok, bhh_tok, bih_ins, bhh_ins);

    // big hoisted GEMM: Xg = tokens @ Wp_tok^T + bp_tok
    gemm_plain_k<<<dim3(G4 / 128, (NINS * TTOK) / 128), 256>>>(
        tokens, EMB, Wp_tok, EMB, bp_tok, Xg, G4, EMB);

    // persistent token-LSTM recurrence + X2g
    recur_persist_k<<<NB_REC, 256>>>(nullptr);

    // persistent DAG + root reduce + final
    dag_persist_k<<<NB_DAG, 256>>>(pidx, pval, Wlin, blin, out);

    (void)in_sizes; (void)n_in; (void)out_size;
}